// round 1
// baseline (speedup 1.0000x reference)
#include <cuda_runtime.h>
#include <math.h>

#define NN   1024
#define BB   16
#define NPIX (NN*NN)
#define BPB  64      // blocks per batch, kernel A
#define TPB  256

struct Cand { float m; float d; int idx; float sal; };

__device__ Cand  g_cand_h[BB][BPB];
__device__ Cand  g_cand_s[BB][BPB];
__device__ int   g_any[BB*BPB];
__device__ float g_loc[BB][4];   // lx, ly, eps
__device__ int   g_anyflag;

__device__ __forceinline__ bool better(const Cand& a, const Cand& b) {
    if (a.m != b.m) return a.m > b.m;       // larger masked saliency wins
    if (a.d != b.d) return a.d < b.d;       // then smaller distance to current loc
    return a.idx < b.idx;                    // then first index (jnp.argmin tie-break)
}

// radius = 1/N^2/2 = 2^-21, exactly representable
#define RADIUS (4.76837158203125e-07f)

// ---------------------------------------------------------------------------
// Kernel A: per-batch fused { cur-mask, masked=hist*sal, max-reduce with
// tie-broken candidate (d = cur_dist, idx), hist-any-nonzero OR }.
// Tracks both variants: _h (hist as given) and _s (hist treated as ones,
// used iff the WHOLE hist tensor is zero).
// ---------------------------------------------------------------------------
__global__ void __launch_bounds__(TPB)
kernelA(const float* __restrict__ sal, const float* __restrict__ hist,
        const float* __restrict__ cur, const float* __restrict__ grid)
{
    __shared__ float r[NN];
    __shared__ Cand sh[TPB];
    __shared__ Cand ss[TPB];

    const int b   = blockIdx.y;
    const int tid = threadIdx.x;

    // r[i] = grid[0][i][0]  (the linspace vector; grid[y][x] = (r[x], r[y]))
    for (int i = tid; i < NN; i += TPB) r[i] = grid[2*i];
    __syncthreads();

    const float cx = cur[2*b], cy = cur[2*b+1];

    const float4* sal4 = (const float4*)(sal  + (size_t)b * NPIX);
    const float4* h4p  = (const float4*)(hist + (size_t)b * NPIX);

    Cand bh; bh.m = -1.0f; bh.d = 3.4e38f; bh.idx = 0x7fffffff; bh.sal = 0.0f;
    Cand bs = bh;
    int any = 0;

    const int nvec = NPIX / 4;
    for (int v = blockIdx.x * TPB + tid; v < nvec; v += BPB * TPB) {
        float4 s4 = sal4[v];
        float4 h4 = h4p[v];
        int p0 = v * 4;
        int y = p0 >> 10, x = p0 & 1023;
        float gy  = r[y];
        float dy  = gy - cy;
        float dy2 = __fmul_rn(dy, dy);
        float sv[4] = {s4.x, s4.y, s4.z, s4.w};
        float hv[4] = {h4.x, h4.y, h4.z, h4.w};
        #pragma unroll
        for (int j = 0; j < 4; j++) {
            float gx = r[x + j];
            float dx = gx - cx;
            // exact: ((dx*dx) + dy2) * 0.5, no FMA contraction
            float d  = __fmul_rn(__fadd_rn(__fmul_rn(dx, dx), dy2), 0.5f);
            float s  = (d <= RADIUS) ? 0.0f : sv[j];
            float h  = hv[j];
            float mh = __fmul_rn(h, s);
            any |= (h != 0.0f);
            int idx = p0 + j;
            Cand ch; ch.m = mh; ch.d = d; ch.idx = idx; ch.sal = s;
            if (better(ch, bh)) bh = ch;
            Cand cs; cs.m = s;  cs.d = d; cs.idx = idx; cs.sal = s;
            if (better(cs, bs)) bs = cs;
        }
    }

    sh[tid] = bh; ss[tid] = bs;
    any = __syncthreads_or(any);   // also acts as the barrier before the tree
    for (int w = TPB / 2; w > 0; w >>= 1) {
        if (tid < w) {
            if (better(sh[tid + w], sh[tid])) sh[tid] = sh[tid + w];
            if (better(ss[tid + w], ss[tid])) ss[tid] = ss[tid + w];
        }
        __syncthreads();
    }
    if (tid == 0) {
        g_cand_h[b][blockIdx.x] = sh[0];
        g_cand_s[b][blockIdx.x] = ss[0];
        g_any[b * BPB + blockIdx.x] = any;
    }
}

// ---------------------------------------------------------------------------
// Kernel B: combine partials. One warp per batch (16 warps / 512 threads).
// ---------------------------------------------------------------------------
__global__ void __launch_bounds__(512)
kernelB(const float* __restrict__ sal, const float* __restrict__ cur,
        const float* __restrict__ grid, float* __restrict__ out)
{
    const int tid = threadIdx.x;
    int any = 0;
    for (int i = tid; i < BB * BPB; i += 512) any |= g_any[i];
    any = __syncthreads_or(any);

    const int warp = tid >> 5, lane = tid & 31;
    if (warp < BB) {
        const int b = warp;
        Cand best; best.m = -1.0f; best.d = 3.4e38f; best.idx = 0x7fffffff; best.sal = 0.0f;
        for (int i = lane; i < BPB; i += 32) {
            Cand c = any ? g_cand_h[b][i] : g_cand_s[b][i];
            if (better(c, best)) best = c;
        }
        #pragma unroll
        for (int o = 16; o > 0; o >>= 1) {
            Cand c;
            c.m   = __shfl_xor_sync(0xffffffffu, best.m,   o);
            c.d   = __shfl_xor_sync(0xffffffffu, best.d,   o);
            c.idx = __shfl_xor_sync(0xffffffffu, best.idx, o);
            c.sal = __shfl_xor_sync(0xffffffffu, best.sal, o);
            if (better(c, best)) best = c;
        }
        if (lane == 0) {
            bool allz = (best.m == 0.0f);   // masked >= 0 always
            int   idx  = best.idx;
            float salv = best.sal;
            if (allz) {
                // reference: argmin of all-inf d -> index 0
                idx = 0;
                float g0x = grid[0], g0y = grid[1];
                float cx = cur[2*b], cy = cur[2*b+1];
                float dx = g0x - cx, dy = g0y - cy;
                float d00 = __fmul_rn(__fadd_rn(__fmul_rn(dx,dx), __fmul_rn(dy,dy)), 0.5f);
                salv = (d00 <= RADIUS) ? 0.0f : sal[(size_t)b * NPIX];
            }
            int py = idx >> 10, px = idx & 1023;
            float lx = 2.0f * ((float)(px + 1) / 1024.0f) - 1.0f;
            float ly = 2.0f * ((float)(py + 1) / 1024.0f) - 1.0f;
            float sm  = fmaxf(salv, 1e-4f);
            float eps = 10.0f / sm;
            out[2*b]     = allz ? 1.0f : lx;
            out[2*b + 1] = allz ? 1.0f : ly;
            g_loc[b][0] = lx; g_loc[b][1] = ly; g_loc[b][2] = eps;
        }
    }
    if (tid == 0) g_anyflag = any;
}

// ---------------------------------------------------------------------------
// Kernel C: mask = exp(-(rbf*eps)^2); hist_out = clip(hist*(1-mask), 0, 1)
// ---------------------------------------------------------------------------
__global__ void __launch_bounds__(256)
kernelC(const float* __restrict__ hist, const float* __restrict__ grid,
        float* __restrict__ out)
{
    __shared__ float r[NN];
    const int b = blockIdx.y;
    for (int i = threadIdx.x; i < NN; i += 256) r[i] = grid[2*i];
    __syncthreads();

    const float lx = g_loc[b][0], ly = g_loc[b][1], eps = g_loc[b][2];
    const int anyh = g_anyflag;

    const float4* h4p  = (const float4*)(hist + (size_t)b * NPIX);
    float4* hout = (float4*)(out + 32 + (size_t)b * NPIX);
    float4* mout = (float4*)(out + 32 + (size_t)BB * NPIX + (size_t)b * NPIX);

    const int nvec = NPIX / 4;
    for (int v = blockIdx.x * 256 + threadIdx.x; v < nvec; v += gridDim.x * 256) {
        float4 h4 = h4p[v];
        if (!anyh) h4 = make_float4(1.f, 1.f, 1.f, 1.f);
        int p0 = v * 4;
        int y = p0 >> 10, x = p0 & 1023;
        float gy  = r[y];
        float dyl = gy - ly;
        float dy2 = __fmul_rn(dyl, dyl);
        float hv[4] = {h4.x, h4.y, h4.z, h4.w};
        float m[4], ho[4];
        #pragma unroll
        for (int j = 0; j < 4; j++) {
            float gx  = r[x + j];
            float dx  = gx - lx;
            float rbf = __fmul_rn(__fadd_rn(__fmul_rn(dx, dx), dy2), 0.5f);
            float t   = __fmul_rn(rbf, eps);
            float mm  = expf(-__fmul_rn(t, t));
            m[j] = mm;
            float hv2 = __fmul_rn(hv[j], 1.0f - mm);
            ho[j] = fminf(fmaxf(hv2, 0.0f), 1.0f);
        }
        hout[v] = make_float4(ho[0], ho[1], ho[2], ho[3]);
        mout[v] = make_float4(m[0], m[1], m[2], m[3]);
    }
}

extern "C" void kernel_launch(void* const* d_in, const int* in_sizes, int n_in,
                              void* d_out, int out_size)
{
    (void)in_sizes; (void)n_in; (void)out_size;
    const float* sal  = (const float*)d_in[0];  // (16,1024,1024)
    const float* hist = (const float*)d_in[1];  // (16,1,1024,1024)
    const float* cur  = (const float*)d_in[2];  // (16,2)
    const float* grid = (const float*)d_in[3];  // (1024,1024,2)
    float* out = (float*)d_out;                 // 32 + 16M (hist) + 16M (mask)

    kernelA<<<dim3(BPB, BB), TPB>>>(sal, hist, cur, grid);
    kernelB<<<1, 512>>>(sal, cur, grid, out);
    kernelC<<<dim3(256, BB), 256>>>(hist, grid, out);
}

// round 2
// speedup vs baseline: 1.2555x; 1.2555x over previous
#include <cuda_runtime.h>
#include <math.h>

#define NN   1024
#define BB   16
#define NPIX (NN*NN)
#define BPB  64      // blocks per batch, kernels A/AS
#define TPB  256
#define NITER 16     // NPIX/4 / (BPB*TPB)

// radius = 1/N^2/2 = 2^-21, exactly representable
#define RADIUS (4.76837158203125e-07f)

__device__ float              g_pm[BB][BPB];   // h-variant partial max
__device__ unsigned long long g_pk[BB][BPB];   // h-variant partial key
__device__ float              g_sm[BB][BPB];   // s-variant (hist==0 fallback)
__device__ unsigned long long g_sk[BB][BPB];
__device__ unsigned           g_any[BB*BPB];
__device__ unsigned           g_ctr = 0;
__device__ int                g_anyflag;
__device__ float              g_loc[BB][4];    // lx, ly, eps

__device__ __forceinline__ void upd_cand(float m, unsigned long long k,
                                         float& bm, unsigned long long& bk) {
    bool u = (m > bm) || (m == bm && k < bk);
    if (u) { bm = m; bk = k; }
}

// ---------------------------------------------------------------------------
// Kernel A: fused { cur-mask, masked=hist*sal, (max,key) reduce, any-OR }.
// key = (d_bits<<20)|idx encodes the (min d, min idx) tie-break.
// Last block reduces the per-block any flags -> g_anyflag.
// ---------------------------------------------------------------------------
__global__ void __launch_bounds__(TPB)
kernelA(const float* __restrict__ sal, const float* __restrict__ hist,
        const float* __restrict__ cur, const float* __restrict__ grid)
{
    __shared__ __align__(16) float r[NN];
    __shared__ float              red_m[TPB];
    __shared__ unsigned long long red_k[TPB];
    __shared__ int                lastBlk;

    const int b   = blockIdx.y;
    const int tid = threadIdx.x;

    for (int i = tid; i < NN; i += TPB) r[i] = grid[2*i];
    __syncthreads();

    const float cx = cur[2*b], cy = cur[2*b+1];
    const float4* sal4 = (const float4*)(sal  + (size_t)b * NPIX);
    const float4* h4p  = (const float4*)(hist + (size_t)b * NPIX);

    float bm = -1.0f; unsigned long long bk = ~0ull;
    unsigned acc = 0u;

    const int base = blockIdx.x * TPB + tid;
    #pragma unroll 2
    for (int it = 0; it < NITER; it++) {
        int v = base + it * (BPB * TPB);
        float4 s4 = __ldcs(&sal4[v]);   // sal never reused -> evict-first
        float4 h4 = h4p[v];             // hist reused by kernelC -> keep in L2
        int p0 = v * 4;
        int y = p0 >> 10, x = p0 & 1023;
        float dy  = r[y] - cy;
        float dy2 = __fmul_rn(dy, dy);
        acc |= (__float_as_uint(h4.x) | __float_as_uint(h4.y) |
                __float_as_uint(h4.z) | __float_as_uint(h4.w));
        float4 gx4 = *(const float4*)&r[x];
        float gx[4] = {gx4.x, gx4.y, gx4.z, gx4.w};
        float sv[4] = {s4.x, s4.y, s4.z, s4.w};
        float hv[4] = {h4.x, h4.y, h4.z, h4.w};
        #pragma unroll
        for (int j = 0; j < 4; j++) {
            float dx = gx[j] - cx;
            float d  = __fmul_rn(__fadd_rn(__fmul_rn(dx, dx), dy2), 0.5f);
            float s  = (d <= RADIUS) ? 0.0f : sv[j];
            float mh = __fmul_rn(hv[j], s);
            unsigned long long key =
                ((unsigned long long)__float_as_uint(d) << 20) | (unsigned)(p0 + j);
            upd_cand(mh, key, bm, bk);
        }
    }

    red_m[tid] = bm; red_k[tid] = bk;
    int anyv = __syncthreads_or((acc << 1) != 0u);   // <<1 kills -0 sign bits
    for (int w = TPB / 2; w > 0; w >>= 1) {
        if (tid < w) upd_cand(red_m[tid + w], red_k[tid + w], red_m[tid], red_k[tid]);
        __syncthreads();
    }
    if (tid == 0) {
        g_pm[b][blockIdx.x] = red_m[0];
        g_pk[b][blockIdx.x] = red_k[0];
        g_any[b * BPB + blockIdx.x] = anyv ? 1u : 0u;
        __threadfence();
        unsigned old = atomicAdd(&g_ctr, 1u);
        lastBlk = (old == (unsigned)(BPB * BB - 1));
    }
    __syncthreads();
    if (lastBlk) {
        unsigned a = 0;
        for (int i = tid; i < BB * BPB; i += TPB) a |= g_any[i];
        int anyAll = __syncthreads_or(a != 0u);
        if (tid == 0) { g_anyflag = anyAll; g_ctr = 0; }
    }
}

// ---------------------------------------------------------------------------
// Kernel AS: fallback scan over sal alone (hist treated as ones). Only runs
// when the whole hist tensor is zero; otherwise every block exits immediately.
// ---------------------------------------------------------------------------
__global__ void __launch_bounds__(TPB)
kernelAS(const float* __restrict__ sal, const float* __restrict__ cur,
         const float* __restrict__ grid)
{
    if (g_anyflag) return;

    __shared__ __align__(16) float r[NN];
    __shared__ float              red_m[TPB];
    __shared__ unsigned long long red_k[TPB];

    const int b   = blockIdx.y;
    const int tid = threadIdx.x;
    for (int i = tid; i < NN; i += TPB) r[i] = grid[2*i];
    __syncthreads();

    const float cx = cur[2*b], cy = cur[2*b+1];
    const float4* sal4 = (const float4*)(sal + (size_t)b * NPIX);

    float bm = -1.0f; unsigned long long bk = ~0ull;
    const int base = blockIdx.x * TPB + tid;
    #pragma unroll 2
    for (int it = 0; it < NITER; it++) {
        int v = base + it * (BPB * TPB);
        float4 s4 = sal4[v];
        int p0 = v * 4;
        int y = p0 >> 10, x = p0 & 1023;
        float dy  = r[y] - cy;
        float dy2 = __fmul_rn(dy, dy);
        float4 gx4 = *(const float4*)&r[x];
        float gx[4] = {gx4.x, gx4.y, gx4.z, gx4.w};
        float sv[4] = {s4.x, s4.y, s4.z, s4.w};
        #pragma unroll
        for (int j = 0; j < 4; j++) {
            float dx = gx[j] - cx;
            float d  = __fmul_rn(__fadd_rn(__fmul_rn(dx, dx), dy2), 0.5f);
            float s  = (d <= RADIUS) ? 0.0f : sv[j];
            unsigned long long key =
                ((unsigned long long)__float_as_uint(d) << 20) | (unsigned)(p0 + j);
            upd_cand(s, key, bm, bk);
        }
    }

    red_m[tid] = bm; red_k[tid] = bk;
    __syncthreads();
    for (int w = TPB / 2; w > 0; w >>= 1) {
        if (tid < w) upd_cand(red_m[tid + w], red_k[tid + w], red_m[tid], red_k[tid]);
        __syncthreads();
    }
    if (tid == 0) {
        g_sm[b][blockIdx.x] = red_m[0];
        g_sk[b][blockIdx.x] = red_k[0];
    }
}

// ---------------------------------------------------------------------------
// Kernel B: combine partials. One warp per batch.
// ---------------------------------------------------------------------------
__global__ void __launch_bounds__(512)
kernelB(const float* __restrict__ sal, const float* __restrict__ cur,
        const float* __restrict__ grid, float* __restrict__ out)
{
    const int tid = threadIdx.x;
    const int any = g_anyflag;
    const int warp = tid >> 5, lane = tid & 31;
    if (warp >= BB) return;
    const int b = warp;

    float bm = -1.0f; unsigned long long bk = ~0ull;
    for (int i = lane; i < BPB; i += 32) {
        float m             = any ? g_pm[b][i] : g_sm[b][i];
        unsigned long long k = any ? g_pk[b][i] : g_sk[b][i];
        upd_cand(m, k, bm, bk);
    }
    #pragma unroll
    for (int o = 16; o > 0; o >>= 1) {
        float m2             = __shfl_xor_sync(0xffffffffu, bm, o);
        unsigned long long k2 = __shfl_xor_sync(0xffffffffu, bk, o);
        upd_cand(m2, k2, bm, bk);
    }
    if (lane == 0) {
        bool allz = (bm == 0.0f);   // masked >= 0 always
        int idx;
        float salv;
        if (allz) {
            idx = 0;   // reference: argmin of all-inf d -> index 0
            float dx = grid[0] - cur[2*b], dyv = grid[1] - cur[2*b+1];
            float d00 = __fmul_rn(__fadd_rn(__fmul_rn(dx,dx), __fmul_rn(dyv,dyv)), 0.5f);
            salv = (d00 <= RADIUS) ? 0.0f : sal[(size_t)b * NPIX];
        } else {
            idx  = (int)(bk & 0xFFFFFu);
            salv = sal[(size_t)b * NPIX + idx];   // m>0 => not cur-masked
        }
        int py = idx >> 10, px = idx & 1023;
        float lx = 2.0f * ((float)(px + 1) / 1024.0f) - 1.0f;
        float ly = 2.0f * ((float)(py + 1) / 1024.0f) - 1.0f;
        float sm  = fmaxf(salv, 1e-4f);
        float eps = 10.0f / sm;
        out[2*b]     = allz ? 1.0f : lx;
        out[2*b + 1] = allz ? 1.0f : ly;
        g_loc[b][0] = lx; g_loc[b][1] = ly; g_loc[b][2] = eps;
    }
}

// ---------------------------------------------------------------------------
// Kernel C: mask = exp(-(rbf*eps)^2); hist_out = clip(hist*(1-mask), 0, 1)
// ---------------------------------------------------------------------------
__global__ void __launch_bounds__(256)
kernelC(const float* __restrict__ hist, const float* __restrict__ grid,
        float* __restrict__ out)
{
    __shared__ __align__(16) float r[NN];
    const int b = blockIdx.y;
    for (int i = threadIdx.x; i < NN; i += 256) r[i] = grid[2*i];
    __syncthreads();

    const float lx = g_loc[b][0], ly = g_loc[b][1], eps = g_loc[b][2];
    const int anyh = g_anyflag;

    const float4* h4p = (const float4*)(hist + (size_t)b * NPIX);
    float4* hout = (float4*)(out + 32 + (size_t)b * NPIX);
    float4* mout = (float4*)(out + 32 + (size_t)BB * NPIX + (size_t)b * NPIX);

    const int nvec = NPIX / 4;
    for (int v = blockIdx.x * 256 + threadIdx.x; v < nvec; v += gridDim.x * 256) {
        float4 h4 = h4p[v];
        if (!anyh) h4 = make_float4(1.f, 1.f, 1.f, 1.f);
        int p0 = v * 4;
        int y = p0 >> 10, x = p0 & 1023;
        float gy  = r[y];
        float dyl = gy - ly;
        float dy2 = __fmul_rn(dyl, dyl);
        float4 gx4 = *(const float4*)&r[x];
        float gx[4] = {gx4.x, gx4.y, gx4.z, gx4.w};
        float hv[4] = {h4.x, h4.y, h4.z, h4.w};
        float m[4], ho[4];
        #pragma unroll
        for (int j = 0; j < 4; j++) {
            float dx  = gx[j] - lx;
            float rbf = __fmul_rn(__fadd_rn(__fmul_rn(dx, dx), dy2), 0.5f);
            float t   = __fmul_rn(rbf, eps);
            float mm  = expf(-__fmul_rn(t, t));
            m[j] = mm;
            float hv2 = __fmul_rn(hv[j], 1.0f - mm);
            ho[j] = fminf(fmaxf(hv2, 0.0f), 1.0f);
        }
        __stcs(&hout[v], make_float4(ho[0], ho[1], ho[2], ho[3]));
        __stcs(&mout[v], make_float4(m[0], m[1], m[2], m[3]));
    }
}

extern "C" void kernel_launch(void* const* d_in, const int* in_sizes, int n_in,
                              void* d_out, int out_size)
{
    (void)in_sizes; (void)n_in; (void)out_size;
    const float* sal  = (const float*)d_in[0];  // (16,1024,1024)
    const float* hist = (const float*)d_in[1];  // (16,1,1024,1024)
    const float* cur  = (const float*)d_in[2];  // (16,2)
    const float* grid = (const float*)d_in[3];  // (1024,1024,2)
    float* out = (float*)d_out;                 // 32 + 16M (hist) + 16M (mask)

    kernelA <<<dim3(BPB, BB), TPB>>>(sal, hist, cur, grid);
    kernelAS<<<dim3(BPB, BB), TPB>>>(sal, cur, grid);
    kernelB <<<1, 512>>>(sal, cur, grid, out);
    kernelC <<<dim3(256, BB), 256>>>(hist, grid, out);
}